// round 1
// baseline (speedup 1.0000x reference)
#include <cuda_runtime.h>
#include <cuda_bf16.h>
#include <cstddef>

// Problem shape (fixed by reference setup_inputs):
//   user  [B=32, U=128, D=256] fp32
//   image [B=32, I=256, D=256] fp32
// Outputs (concatenated in d_out):
//   out_user [B,U,D] = user  * img_sum[b,1,D]
//   out_img  [B,I,D] = image * user_sum[b,1,D]

#define BB 32
#define UU 128
#define II 256
#define DD 256

#define DCHUNK 64            // fp32 columns per CTA
#define NCHUNK (DD / DCHUNK) // 4
#define TX 16                // float4 lanes (16*4 = 64 floats)
#define TY 16                // row groups
#define NTHREADS (TX * TY)   // 256

// dynamic smem layout (in float4 units)
//   su   : U  * TX   = 2048
//   si   : I  * TX   = 4096
//   redU : TY * TX   = 256
//   redI : TY * TX   = 256
//   usum : TX        = 16
//   isum : TX        = 16
#define SMEM_F4 (UU * TX + II * TX + 2 * TY * TX + 2 * TX)
#define SMEM_BYTES (SMEM_F4 * (int)sizeof(float4))

__device__ __forceinline__ float4 f4add(float4 a, float4 b) {
    return make_float4(a.x + b.x, a.y + b.y, a.z + b.z, a.w + b.w);
}
__device__ __forceinline__ float4 f4mul(float4 a, float4 b) {
    return make_float4(a.x * b.x, a.y * b.y, a.z * b.z, a.w * b.w);
}

__global__ __launch_bounds__(NTHREADS, 1)
void ExternalInteraction_65609920413984_kernel(
    const float* __restrict__ user,
    const float* __restrict__ img,
    float* __restrict__ out_user,
    float* __restrict__ out_img)
{
    extern __shared__ float4 smem[];
    float4* su   = smem;                 // [U][TX]
    float4* si   = su   + UU * TX;       // [I][TX]
    float4* redU = si   + II * TX;       // [TY][TX]
    float4* redI = redU + TY * TX;       // [TY][TX]
    float4* usum = redI + TY * TX;       // [TX]
    float4* isum = usum + TX;            // [TX]

    const int b     = blockIdx.x >> 2;        // / NCHUNK
    const int chunk = blockIdx.x & (NCHUNK - 1);
    const int d0    = chunk * DCHUNK;

    const int tx = threadIdx.x & (TX - 1);
    const int ty = threadIdx.x >> 4;
    const int d  = d0 + tx * 4;

    const float4* up = reinterpret_cast<const float4*>(user + (size_t)b * UU * DD + d);
    const float4* ip = reinterpret_cast<const float4*>(img  + (size_t)b * II * DD + d);
    const int rs = DD / 4;   // row stride in float4

    // ---- Phase 1: stream tiles, accumulate partial column sums, cache in smem
    float4 au = make_float4(0.f, 0.f, 0.f, 0.f);
    float4 ai = make_float4(0.f, 0.f, 0.f, 0.f);

    #pragma unroll
    for (int k = 0; k < UU / TY; k++) {          // 8 iterations
        int r = ty + k * TY;
        float4 v = up[(size_t)r * rs];
        su[r * TX + tx] = v;
        au = f4add(au, v);
    }
    #pragma unroll
    for (int k = 0; k < II / TY; k++) {          // 16 iterations
        int r = ty + k * TY;
        float4 v = ip[(size_t)r * rs];
        si[r * TX + tx] = v;
        ai = f4add(ai, v);
    }

    redU[ty * TX + tx] = au;
    redI[ty * TX + tx] = ai;
    __syncthreads();

    if (ty == 0) {
        float4 s = make_float4(0.f, 0.f, 0.f, 0.f);
        float4 t = make_float4(0.f, 0.f, 0.f, 0.f);
        #pragma unroll
        for (int k = 0; k < TY; k++) {
            s = f4add(s, redU[k * TX + tx]);
            t = f4add(t, redI[k * TX + tx]);
        }
        usum[tx] = s;
        isum[tx] = t;
    }
    __syncthreads();

    const float4 us  = usum[tx];   // sum over u of user[b,:,d..d+3]
    const float4 is4 = isum[tx];   // sum over i of img [b,:,d..d+3]

    // ---- Phase 2: scale cached tiles, write out (coalesced float4 stores)
    float4* ou = reinterpret_cast<float4*>(out_user + (size_t)b * UU * DD + d);
    float4* oi = reinterpret_cast<float4*>(out_img  + (size_t)b * II * DD + d);

    #pragma unroll
    for (int k = 0; k < UU / TY; k++) {
        int r = ty + k * TY;
        ou[(size_t)r * rs] = f4mul(su[r * TX + tx], is4);
    }
    #pragma unroll
    for (int k = 0; k < II / TY; k++) {
        int r = ty + k * TY;
        oi[(size_t)r * rs] = f4mul(si[r * TX + tx], us);
    }
}

extern "C" void kernel_launch(void* const* d_in, const int* in_sizes, int n_in,
                              void* d_out, int out_size)
{
    (void)in_sizes; (void)n_in; (void)out_size;
    const float* user = (const float*)d_in[0];
    const float* img  = (const float*)d_in[1];
    float* out_user = (float*)d_out;
    float* out_img  = (float*)d_out + (size_t)BB * UU * DD;

    cudaFuncSetAttribute(ExternalInteraction_65609920413984_kernel,
                         cudaFuncAttributeMaxDynamicSharedMemorySize, SMEM_BYTES);

    ExternalInteraction_65609920413984_kernel
        <<<BB * NCHUNK, NTHREADS, SMEM_BYTES>>>(user, img, out_user, out_img);
}